// round 5
// baseline (speedup 1.0000x reference)
#include <cuda_runtime.h>
#include <cuda_bf16.h>

// RoIAlign1D: feat [B,T,D] f32, spans [B,K,2] i32, lengths [B] i32 -> out [B,K,P,D] f32
// P = 16, D = 512 (128 float4).
//
// R5: persistent single-wave grid. 1776 blocks (148 SM x 12 resident), each
// grid-strides over the 4096 (RoI, 4-sample-group) items. Per item: span math
// once, 8 independent LDG.128 per thread (MLP=8), lerp (FADD+FFMA form),
// __stcs streaming stores. 32-bit offsets, regs capped for 12 blocks/SM.

#define P_SAMPLES 16
#define PG 4   // samples per work item

__global__ void __launch_bounds__(128, 12) roialign1d_kernel(
    const float4* __restrict__ feat,   // [B, T, 128]
    const int*    __restrict__ spans,  // [B, K, 2]
    const int*    __restrict__ lengths,// [B]
    float4*       __restrict__ out,    // [B, K, P, 128]
    int K, int T, int D4, int nwork, int nblk)
{
    const int tid = threadIdx.x;                 // d4 lane, 0..127

    for (int it = blockIdx.x; it < nwork; it += nblk) {
        const int pg = it & 3;
        const int bk = it >> 2;                  // b*K + k
        const int b  = bk / K;

        // ---- span math, once per item (uniform across block) ----
        const int Lm1 = __ldg(&lengths[b]) - 1;
        int a0 = __ldg(&spans[bk * 2 + 0]);
        int a1 = __ldg(&spans[bk * 2 + 1]);
        a0 = min(max(a0, 0), Lm1);
        a1 = min(max(a1, 0), Lm1);
        const int s     = min(a0, a1);
        const int segm1 = max(a0, a1) - s;       // seglen - 1
        const float segf = (float)segm1;

        const int fbase = (b * T + s) * D4 + tid;
        const int obase = (bk * P_SAMPLES + pg * PG) * D4 + tid;

        float4 f0[PG], f1[PG];
        float  w[PG];
        #pragma unroll
        for (int u = 0; u < PG; u++) {
            const int pp = pg * PG + u;
            const float t   = (float)pp / (float)(P_SAMPLES - 1);
            const float idx = t * segf;
            int i0 = (int)floorf(idx);
            i0 = min(i0, segm1);
            const int i1 = min(i0 + 1, segm1);
            w[u] = idx - (float)i0;
            f0[u] = feat[fbase + i0 * D4];
            f1[u] = feat[fbase + i1 * D4];
        }
        #pragma unroll
        for (int u = 0; u < PG; u++) {
            // (1-w)*f0 + w*f1 == f0 + w*(f1-f0): FADD + FFMA per component
            float4 r;
            r.x = fmaf(w[u], f1[u].x - f0[u].x, f0[u].x);
            r.y = fmaf(w[u], f1[u].y - f0[u].y, f0[u].y);
            r.z = fmaf(w[u], f1[u].z - f0[u].z, f0[u].z);
            r.w = fmaf(w[u], f1[u].w - f0[u].w, f0[u].w);
            __stcs(&out[obase + u * D4], r);     // streaming store: keep L2 for feat
        }
    }
}

extern "C" void kernel_launch(void* const* d_in, const int* in_sizes, int n_in,
                              void* d_out, int out_size)
{
    const float* feat    = (const float*)d_in[0];
    const int*   spans   = (const int*)d_in[1];
    const int*   lengths = (const int*)d_in[2];
    float*       out     = (float*)d_out;

    const int B  = in_sizes[2];                      // 16
    const int K  = in_sizes[1] / (2 * B);            // 64
    const int TD = in_sizes[0] / B;                  // T*D
    const int D  = out_size / (B * K * P_SAMPLES);   // 512
    const int T  = TD / D;                           // 4096
    const int D4 = D / 4;                            // 128

    const int nwork = B * K * (P_SAMPLES / PG);      // 4096
    const int nblk  = 148 * 12;                      // one full resident wave
    roialign1d_kernel<<<nblk, D4>>>(
        (const float4*)feat, spans, lengths, (float4*)out, K, T, D4, nwork, nblk);
}

// round 6
// speedup vs baseline: 1.2149x; 1.2149x over previous
#include <cuda_runtime.h>
#include <cuda_bf16.h>

// RoIAlign1D: feat [B,T,D] f32, spans [B,K,2] i32, lengths [B] i32 -> out [B,K,P,D] f32
// P = 16, D = 512 (128 float4).
//
// R6: one block per (RoI, 2-sample group). Grid = B*K*8 = 8192 blocks, 128
// threads. 4 independent LDG.128 per thread (MLP=4 -- half of R4's queue
// burst), regs ~28 -> __launch_bounds__(128,16) hits the 64-warp/SM cap.
// Trades some per-thread MLP for full occupancy to reduce cross-CTA L1tex
// queue spread (B300 spr_max model: oe*MLP_p1 96 -> 64).

#define P_SAMPLES 16
#define PG 2   // samples per block

__global__ void __launch_bounds__(128, 16) roialign1d_kernel(
    const float4* __restrict__ feat,   // [B, T, 128]
    const int*    __restrict__ spans,  // [B, K, 2]
    const int*    __restrict__ lengths,// [B]
    float4*       __restrict__ out,    // [B, K, P, 128]
    int K, int T, int D4)
{
    const int blk = blockIdx.x;                  // bk*8 + pg
    const int pg  = blk & 7;
    const int bk  = blk >> 3;                    // b*K + k
    const int b   = bk / K;
    const int tid = threadIdx.x;                 // d4 lane, 0..127

    // ---- span math, once per block (uniform) ----
    const int Lm1 = __ldg(&lengths[b]) - 1;
    int a0 = __ldg(&spans[bk * 2 + 0]);
    int a1 = __ldg(&spans[bk * 2 + 1]);
    a0 = min(max(a0, 0), Lm1);
    a1 = min(max(a1, 0), Lm1);
    const int s     = min(a0, a1);
    const int segm1 = max(a0, a1) - s;           // seglen - 1
    const float segf = (float)segm1;

    const int fbase = (b * T + s) * D4 + tid;
    const int obase = (bk * P_SAMPLES + pg * PG) * D4 + tid;

    float4 f0[PG], f1[PG];
    float  w[PG];
    #pragma unroll
    for (int u = 0; u < PG; u++) {
        const int pp = pg * PG + u;
        const float t   = (float)pp / (float)(P_SAMPLES - 1);
        const float idx = t * segf;
        int i0 = (int)floorf(idx);
        i0 = min(i0, segm1);
        const int i1 = min(i0 + 1, segm1);
        w[u] = idx - (float)i0;
        f0[u] = feat[fbase + i0 * D4];
        f1[u] = feat[fbase + i1 * D4];
    }
    #pragma unroll
    for (int u = 0; u < PG; u++) {
        float4 r;
        r.x = fmaf(w[u], f1[u].x - f0[u].x, f0[u].x);
        r.y = fmaf(w[u], f1[u].y - f0[u].y, f0[u].y);
        r.z = fmaf(w[u], f1[u].z - f0[u].z, f0[u].z);
        r.w = fmaf(w[u], f1[u].w - f0[u].w, f0[u].w);
        __stcs(&out[obase + u * D4], r);         // streaming store: keep L2 for feat
    }
}

extern "C" void kernel_launch(void* const* d_in, const int* in_sizes, int n_in,
                              void* d_out, int out_size)
{
    const float* feat    = (const float*)d_in[0];
    const int*   spans   = (const int*)d_in[1];
    const int*   lengths = (const int*)d_in[2];
    float*       out     = (float*)d_out;

    const int B  = in_sizes[2];                      // 16
    const int K  = in_sizes[1] / (2 * B);            // 64
    const int TD = in_sizes[0] / B;                  // T*D
    const int D  = out_size / (B * K * P_SAMPLES);   // 512
    const int T  = TD / D;                           // 4096
    const int D4 = D / 4;                            // 128

    const int nblocks = B * K * (P_SAMPLES / PG);    // 8192
    roialign1d_kernel<<<nblocks, D4>>>(
        (const float4*)feat, spans, lengths, (float4*)out, K, T, D4);
}

// round 7
// speedup vs baseline: 1.2186x; 1.0030x over previous
#include <cuda_runtime.h>
#include <cuda_bf16.h>
#include <cstdint>

// RoIAlign1D: feat [B,T,D] f32, spans [B,K,2] i32, lengths [B] i32 -> out [B,K,P,D] f32
// P = 16, D = 512 (128 float4).
//
// R7: 256-thread blocks; each block = one RoI x 4 samples (two 2-sample groups,
// one per 128-thread half). Grid = B*K*4 = 4096. Per thread: 4 independent
// LDG.128 (MLP=4), packed f32x2 lerp (mul.rn.f32x2 + fma.rn.f32x2 -- ptxas
// never emits these from plain C++), __stcs streaming stores, 32-bit offsets.
// __launch_bounds__(256,8) -> 64 warps/SM cap (regs must stay <= 32).

#define P_SAMPLES 16
#define PG 2   // samples per 128-thread half-block

// r = wm2*f0 + w2*f1, two fp32 lanes at a time
__device__ __forceinline__ uint64_t lerp_f32x2(uint64_t f0, uint64_t f1,
                                               uint64_t w2, uint64_t wm2) {
    uint64_t t, r;
    asm("mul.rn.f32x2 %0, %1, %2;" : "=l"(t) : "l"(f0), "l"(wm2));
    asm("fma.rn.f32x2 %0, %1, %2, %3;" : "=l"(r) : "l"(f1), "l"(w2), "l"(t));
    return r;
}

__global__ void __launch_bounds__(256, 8) roialign1d_kernel(
    const float4* __restrict__ feat,   // [B, T, 128]
    const int*    __restrict__ spans,  // [B, K, 2]
    const int*    __restrict__ lengths,// [B]
    float4*       __restrict__ out,    // [B, K, P, 128]
    int K, int T, int D4)
{
    const int blk = blockIdx.x;                  // bk*4 + g
    const int g   = blk & 3;                     // which 4-sample chunk
    const int bk  = blk >> 2;                    // b*K + k
    const int b   = bk / K;
    const int half = threadIdx.x >> 7;           // 0 or 1: which 2-sample group
    const int tid  = threadIdx.x & 127;          // d4 lane
    const int pg   = g * 2 + half;               // 2-sample group id, 0..7

    // ---- span math, uniform across the whole 256-thread block ----
    const int Lm1 = __ldg(&lengths[b]) - 1;
    int a0 = __ldg(&spans[bk * 2 + 0]);
    int a1 = __ldg(&spans[bk * 2 + 1]);
    a0 = min(max(a0, 0), Lm1);
    a1 = min(max(a1, 0), Lm1);
    const int s     = min(a0, a1);
    const int segm1 = max(a0, a1) - s;           // seglen - 1
    const float segf = (float)segm1;

    const int fbase = (b * T + s) * D4 + tid;
    const int obase = (bk * P_SAMPLES + pg * PG) * D4 + tid;

    union V { float4 v; uint64_t u[2]; };
    V f0[PG], f1[PG];
    float w[PG];
    #pragma unroll
    for (int u = 0; u < PG; u++) {
        const int pp = pg * PG + u;
        const float t   = (float)pp / (float)(P_SAMPLES - 1);  // const-folded
        const float idx = t * segf;
        int i0 = (int)floorf(idx);
        i0 = min(i0, segm1);
        const int i1 = min(i0 + 1, segm1);
        w[u] = idx - (float)i0;
        f0[u].v = feat[fbase + i0 * D4];
        f1[u].v = feat[fbase + i1 * D4];
    }
    #pragma unroll
    for (int u = 0; u < PG; u++) {
        const float wm = 1.0f - w[u];
        uint64_t w2, wm2;
        asm("mov.b64 %0, {%1, %1};" : "=l"(w2)  : "f"(w[u]));
        asm("mov.b64 %0, {%1, %1};" : "=l"(wm2) : "f"(wm));
        V r;
        r.u[0] = lerp_f32x2(f0[u].u[0], f1[u].u[0], w2, wm2);
        r.u[1] = lerp_f32x2(f0[u].u[1], f1[u].u[1], w2, wm2);
        __stcs(&out[obase + u * D4], r.v);       // streaming store: keep L2 for feat
    }
}

extern "C" void kernel_launch(void* const* d_in, const int* in_sizes, int n_in,
                              void* d_out, int out_size)
{
    const float* feat    = (const float*)d_in[0];
    const int*   spans   = (const int*)d_in[1];
    const int*   lengths = (const int*)d_in[2];
    float*       out     = (float*)d_out;

    const int B  = in_sizes[2];                      // 16
    const int K  = in_sizes[1] / (2 * B);            // 64
    const int TD = in_sizes[0] / B;                  // T*D
    const int D  = out_size / (B * K * P_SAMPLES);   // 512
    const int T  = TD / D;                           // 4096
    const int D4 = D / 4;                            // 128

    const int nblocks = B * K * 4;                   // 4096
    roialign1d_kernel<<<nblocks, 2 * D4>>>(
        (const float4*)feat, spans, lengths, (float4*)out, K, T, D4);
}